// round 16
// baseline (speedup 1.0000x reference)
#include <cuda_runtime.h>
#include <cuda_fp16.h>
#include <cstdint>
#include <cstddef>

// ---------------------------------------------------------------------------
// Problem dims
// ---------------------------------------------------------------------------
#define NROWS 16384
#define INF   512
#define OUTF  256

#define PH    48             // smem pitch in halves (96 B) for all fp16 tiles
#define KC    32             // K elems per pipeline stage (2 k16 blocks)
#define NSTAGE 3

// ---- Unified GEMM tiling: 112(M) x 256(N) per CTA, 148 CTAs ----
#define TILE_M 112                                   // 7 x 16-row blocks
#define NMI    7
#define A_HALVES (TILE_M * PH)                       // 5376
#define B_HALVES (OUTF * PH)                         // 12288
#define STAGE_BYTES ((A_HALVES + B_HALVES) * 2)      // 35328
#define SMEM_BYTES (NSTAGE * STAGE_BYTES)            // 105984
#define NCTA 148
#define MBLOCKS (NROWS / 16)                         // 1024

// within-16-block k permutation for fp16 operands:
//   logical k -> phys = 4*((k>>1)&3) + 2*((k>>3)&1) + (k&1)
// => thread t's m16n8k16 halves {2t,2t+1,2t+8,2t+9} land at phys [4t..4t+3] (one LDS.64)

// ---------------------------------------------------------------------------
// Scratch (__device__ globals: allocation-free)
// ---------------------------------------------------------------------------
__device__ __align__(256) __half g_gT [(size_t)OUTF * NROWS];  // g^T, fp16 rn, perm16 k-layout

// ---------------------------------------------------------------------------
// Helpers
// ---------------------------------------------------------------------------
__device__ __forceinline__ uint32_t smem_u32(const void* p) {
    uint32_t a;
    asm("{ .reg .u64 t; cvta.to.shared.u64 t, %1; cvt.u32.u64 %0, t; }" : "=r"(a) : "l"(p));
    return a;
}

__device__ __forceinline__ void cp16(uint32_t dst_smem, const void* src) {
    asm volatile("cp.async.cg.shared.global [%0], [%1], 16;"
                 :: "r"(dst_smem), "l"(src) : "memory");
}

__device__ __forceinline__ uint32_t f2h2(float lo, float hi) {
    uint32_t r;
    asm("cvt.rn.f16x2.f32 %0, %2, %1;" : "=r"(r) : "f"(lo), "f"(hi));
    return r;
}

__device__ __forceinline__ void mma_f16(float* d, const uint32_t* a, uint32_t b0, uint32_t b1) {
    asm volatile(
        "mma.sync.aligned.m16n8k16.row.col.f32.f16.f16.f32 "
        "{%0,%1,%2,%3}, {%4,%5,%6,%7}, {%8,%9}, {%0,%1,%2,%3};"
        : "+f"(d[0]), "+f"(d[1]), "+f"(d[2]), "+f"(d[3])
        : "r"(a[0]), "r"(a[1]), "r"(a[2]), "r"(a[3]),
          "r"(b0), "r"(b1));
}

// pack 16 consecutive logical-k fp32 into 8 perm16-ordered f16x2 words
__device__ __forceinline__ void pack16(const float* v, float scale, uint32_t* w) {
    #pragma unroll
    for (int q = 0; q < 4; ++q) {
        w[2 * q + 0] = f2h2(scale * v[2 * q + 0], scale * v[2 * q + 1]);
        w[2 * q + 1] = f2h2(scale * v[2 * q + 8], scale * v[2 * q + 9]);
    }
}

__device__ __forceinline__ void sts8(uint32_t dst, const uint32_t* w) {
    asm volatile("st.shared.v4.b32 [%0], {%1,%2,%3,%4};"
                 :: "r"(dst), "r"(w[0]), "r"(w[1]), "r"(w[2]), "r"(w[3]) : "memory");
    asm volatile("st.shared.v4.b32 [%0], {%1,%2,%3,%4};"
                 :: "r"(dst + 16), "r"(w[4]), "r"(w[5]), "r"(w[6]), "r"(w[7]) : "memory");
}

// ---------------------------------------------------------------------------
// Unified fp16 mma.sync GEMM, 148 CTAs, CTA = 112(M) x 256(N).
//   CTA b covers 7 x 16-row blocks starting at block min(7b, 1017) (tail CTAs
//   overlap; duplicate writes are byte-identical). 8 warps own N-slices of 32.
//   A fp32 in gmem -> LDG/cvt/STS (perm16 smem).
//   MODE 0 (GEMM1): A=feature scaled by hat_d at cvt; B=W fp32 in gmem,
//                   converted per-stage LDG/cvt/STS (no prep pass, no g_wrn);
//                   writes g_gT[n][perm16-scattered m] = half_rn(D[m][n]).
//   MODE 1 (GEMM2): A=adjacency (unscaled); B=g_gT fp16 perm16 via cp.async;
//                   out[m][n] = hat_d[m]*(D[m][n] + gT_perm[n][m]) + b[n].
// ---------------------------------------------------------------------------
template <int MODE>
__global__ void __launch_bounds__(256, 1)
gemm_f16_kernel(const float* __restrict__ Ap, int a_ld,
                const void* __restrict__ Bp, int b_ld,
                int nstages,
                const float* __restrict__ hat_d,
                const float* __restrict__ bias,
                float* __restrict__ out)
{
    extern __shared__ char smraw[];
    const int tid = threadIdx.x;
    const int bid = blockIdx.x;
    const int wid = tid >> 5;     // 0..7 = N slice
    const int lane = tid & 31;
    const int g = lane >> 2;
    const int t = lane & 3;

    int mblock = 7 * bid;
    if (mblock > MBLOCKS - NMI) mblock = MBLOCKS - NMI;
    const int mstart = mblock * 16;

    float acc[NMI][4][4];
    #pragma unroll
    for (int mi = 0; mi < NMI; ++mi)
        #pragma unroll
        for (int ni = 0; ni < 4; ++ni)
            #pragma unroll
            for (int r = 0; r < 4; ++r)
                acc[mi][ni][r] = 0.0f;

    const float* Agm = Ap + (size_t)mstart * a_ld;

    // A staging: threads 0..223 own (row = tid>>1, kblock = tid&1)
    const int a_row = tid >> 1;
    const int a_kb  = tid & 1;
    const bool a_act = (a_row < TILE_M);
    const float* a_src_base = Agm + (size_t)a_row * a_ld + a_kb * 16;
    const float hd_s = (MODE == 0 && a_act) ? __ldg(hat_d + mstart + a_row) : 1.0f;
    float a_stage[16];

    auto ldgA = [&](int s) {
        if (!a_act) return;
        const float* p = a_src_base + s * KC;
        #pragma unroll
        for (int i = 0; i < 4; ++i) {
            float4 v = __ldg(reinterpret_cast<const float4*>(p + 4 * i));
            a_stage[4 * i + 0] = v.x;
            a_stage[4 * i + 1] = v.y;
            a_stage[4 * i + 2] = v.z;
            a_stage[4 * i + 3] = v.w;
        }
    };
    auto stsA = [&](int s) {
        if (!a_act) return;
        __half* As = reinterpret_cast<__half*>(smraw + (s % NSTAGE) * STAGE_BYTES);
        uint32_t w[8];
        pack16(a_stage, (MODE == 0) ? hd_s : 1.0f, w);
        sts8(smem_u32(As + a_row * PH + a_kb * 16), w);
    };

    // ---- B staging ----
    // MODE 0: B = W fp32 -> regs -> cvt -> perm16 STS. Thread owns row=tid, 32 k.
    const float* Wgm = (MODE == 0) ? reinterpret_cast<const float*>(Bp) : nullptr;
    float b_stage[MODE == 0 ? 32 : 1];

    auto ldgB = [&](int s) {
        if (MODE != 0) return;
        const float* p = Wgm + (size_t)tid * b_ld + s * KC;
        #pragma unroll
        for (int i = 0; i < 8; ++i) {
            float4 v = __ldg(reinterpret_cast<const float4*>(p + 4 * i));
            b_stage[4 * i + 0] = v.x;
            b_stage[4 * i + 1] = v.y;
            b_stage[4 * i + 2] = v.z;
            b_stage[4 * i + 3] = v.w;
        }
    };
    auto stsB = [&](int s) {
        if (MODE != 0) return;
        __half* Bs = reinterpret_cast<__half*>(smraw + (s % NSTAGE) * STAGE_BYTES) + A_HALVES;
        #pragma unroll
        for (int kb = 0; kb < 2; ++kb) {
            uint32_t w[8];
            pack16(b_stage + kb * 16, 1.0f, w);
            sts8(smem_u32(Bs + tid * PH + kb * 16), w);
        }
    };
    // MODE 1: B fp16 perm16 via cp.async
    const __half* Bh = (MODE == 1) ? reinterpret_cast<const __half*>(Bp) : nullptr;
    auto cpB = [&](int s) {
        if (MODE != 1) return;
        __half* Bs = reinterpret_cast<__half*>(smraw + (s % NSTAGE) * STAGE_BYTES) + A_HALVES;
        const int k0 = s * KC;
        #pragma unroll
        for (int i = 0; i < 4; ++i) {
            int v = tid + i * 256;
            int row = v >> 2, j = v & 3;
            cp16(smem_u32(Bs + row * PH + j * 8),
                 Bh + (size_t)row * b_ld + k0 + j * 8);
        }
    };

    // ---- prologue ----
    ldgA(0);
    if (MODE == 0) ldgB(0);
    stsA(0);
    if (MODE == 0) stsB(0);
    ldgA(1);
    if (MODE == 0) ldgB(1);
    if (MODE == 1) {
        cpB(0);
        asm volatile("cp.async.commit_group;" ::: "memory");
        cpB(1);
        asm volatile("cp.async.commit_group;" ::: "memory");
    }

    for (int s = 0; s < nstages; ++s) {
        if (MODE == 1)
            asm volatile("cp.async.wait_group 1;" ::: "memory");
        __syncthreads();   // stage s smem visible; all warps past compute(s-1)

        if (s + 1 < nstages) { stsA(s + 1); if (MODE == 0) stsB(s + 1); }
        if (s + 2 < nstages) {
            if (MODE == 1) cpB(s + 2);
            ldgA(s + 2);
            if (MODE == 0) ldgB(s + 2);
        }
        if (MODE == 1)
            asm volatile("cp.async.commit_group;" ::: "memory");

        const __half* As = reinterpret_cast<const __half*>(smraw + (s % NSTAGE) * STAGE_BYTES);
        const __half* Bs = As + A_HALVES;
        const __half* Abase = As + g * PH + 4 * t;
        const __half* Bbase = Bs + (wid * 32 + g) * PH + 4 * t;

        #pragma unroll
        for (int kk = 0; kk < 2; ++kk) {
            uint2 bv[4];
            #pragma unroll
            for (int ni = 0; ni < 4; ++ni)
                bv[ni] = *reinterpret_cast<const uint2*>(Bbase + ni * 8 * PH + kk * 16);
            #pragma unroll
            for (int mi = 0; mi < NMI; ++mi) {
                const __half* p = Abase + mi * 16 * PH + kk * 16;
                uint2 lo = *reinterpret_cast<const uint2*>(p);
                uint2 hi = *reinterpret_cast<const uint2*>(p + 8 * PH);
                uint32_t a[4] = {lo.x, hi.x, lo.y, hi.y};
                #pragma unroll
                for (int ni = 0; ni < 4; ++ni)
                    mma_f16(acc[mi][ni], a, bv[ni].x, bv[ni].y);
            }
        }
    }

    // ---- epilogue ----
    const int nbase = wid * 32;
    const int pg = 4 * (g >> 1) + (g & 1);

    if (MODE == 0) {
        #pragma unroll
        for (int mi = 0; mi < NMI; ++mi) {
            int r0p = mstart + mi * 16 + pg;
            int r1p = r0p + 2;
            #pragma unroll
            for (int ni = 0; ni < 4; ++ni) {
                int c0 = nbase + ni * 8 + 2 * t;
                int c1 = c0 + 1;
                g_gT[(size_t)c0 * NROWS + r0p] = __float2half_rn(acc[mi][ni][0]);
                g_gT[(size_t)c1 * NROWS + r0p] = __float2half_rn(acc[mi][ni][1]);
                g_gT[(size_t)c0 * NROWS + r1p] = __float2half_rn(acc[mi][ni][2]);
                g_gT[(size_t)c1 * NROWS + r1p] = __float2half_rn(acc[mi][ni][3]);
            }
        }
    } else {
        #pragma unroll
        for (int mi = 0; mi < NMI; ++mi) {
            int r0 = mstart + mi * 16 + g;
            int r1 = r0 + 8;
            int r0p = mstart + mi * 16 + pg;
            int r1p = r0p + 2;
            float h0 = __ldg(hat_d + r0);
            float h1 = __ldg(hat_d + r1);
            #pragma unroll
            for (int ni = 0; ni < 4; ++ni) {
                int c0 = nbase + ni * 8 + 2 * t;
                int c1 = c0 + 1;
                float b0v = __ldg(bias + c0);
                float b1v = __ldg(bias + c1);
                float g00 = __half2float(g_gT[(size_t)c0 * NROWS + r0p]);
                float g01 = __half2float(g_gT[(size_t)c1 * NROWS + r0p]);
                float g10 = __half2float(g_gT[(size_t)c0 * NROWS + r1p]);
                float g11 = __half2float(g_gT[(size_t)c1 * NROWS + r1p]);
                float2 v0, v1;
                v0.x = fmaf(h0, acc[mi][ni][0] + g00, b0v);
                v0.y = fmaf(h0, acc[mi][ni][1] + g01, b1v);
                v1.x = fmaf(h1, acc[mi][ni][2] + g10, b0v);
                v1.y = fmaf(h1, acc[mi][ni][3] + g11, b1v);
                *reinterpret_cast<float2*>(out + (size_t)r0 * OUTF + c0) = v0;
                *reinterpret_cast<float2*>(out + (size_t)r1 * OUTF + c0) = v1;
            }
        }
    }
}

// ---------------------------------------------------------------------------
// Host side
// ---------------------------------------------------------------------------
extern "C" void kernel_launch(void* const* d_in, const int* in_sizes, int n_in,
                              void* d_out, int out_size) {
    const float *A = nullptr, *hat_d = nullptr, *feature = nullptr,
                *W = nullptr, *b = nullptr;
    for (int i = 0; i < n_in; ++i) {
        switch (in_sizes[i]) {
            case NROWS:       hat_d   = (const float*)d_in[i]; break;   // 16384
            case OUTF:        b       = (const float*)d_in[i]; break;   // 256
            case OUTF * INF:  W       = (const float*)d_in[i]; break;   // 131072
            case NROWS * INF: feature = (const float*)d_in[i]; break;   // 8388608
            default:          A       = (const float*)d_in[i]; break;   // 16384*16384
        }
    }

    void* p_gT = nullptr;
    cudaGetSymbolAddress(&p_gT, g_gT);

    static bool attr_set = false;
    if (!attr_set) {
        cudaFuncSetAttribute(gemm_f16_kernel<0>,
                             cudaFuncAttributeMaxDynamicSharedMemorySize, SMEM_BYTES);
        cudaFuncSetAttribute(gemm_f16_kernel<1>,
                             cudaFuncAttributeMaxDynamicSharedMemorySize, SMEM_BYTES);
        attr_set = true;
    }

    // GEMM1: g^T = ((hat_d.*feature) @ W^T)^T, K = 512 -> 16 stages
    //        (W converted fp32->fp16/perm16 in-kernel; no prep pass)
    gemm_f16_kernel<0><<<NCTA, 256, SMEM_BYTES>>>(
        feature, INF, W, INF,
        INF / KC, hat_d, nullptr, nullptr);

    // GEMM2: out = hat_d*(A@g + g) + b, K = 16384 -> 512 stages
    gemm_f16_kernel<1><<<NCTA, 256, SMEM_BYTES>>>(
        A, NROWS, p_gT, NROWS,
        NROWS / KC, hat_d, b, (float*)d_out);

    (void)out_size;
}